// round 5
// baseline (speedup 1.0000x reference)
#include <cuda_runtime.h>
#include <cstdint>

// Dendrite: out[b,d] = sum_{v=1..255} lin_w[v-1] * prod_{s: bit(7-s) of v} p_s + lin_b,
//   p_s = sigmoid(k*(w*x-q)).
// Evaluated as a multilinear polynomial in (p_0..p_7) with coefficient table
// c[v] (c[0]=0) via iterated Horner: exactly 255 FMA per output, no subset-
// product tables. v bit j <-> variable p_{7-j}.
// T=2 batch rows per thread amortize the coefficient stream and double ILP.

static constexpr int B = 8192;
static constexpr int D = 32;
static constexpr int S = 8;
static constexpr int T = 2;   // batch rows per thread

__device__ __forceinline__ float fast_sigmoid_prehalved(float arg_half) {
    // sigmoid(a) = 0.5*tanh(a/2)+0.5 ; caller supplies a/2.
    float t;
    asm("tanh.approx.f32 %0, %1;" : "=f"(t) : "f"(arg_half));
    return fmaf(0.5f, t, 0.5f);
}

__global__ __launch_bounds__(128, 7)
void dendrite_kernel(const float* __restrict__ x,      // [B, 1, S]
                     const float* __restrict__ k,      // [D, S]
                     const float* __restrict__ w,      // [D, S]
                     const float* __restrict__ q,      // [D, S]
                     const float* __restrict__ lin_w,  // [1, 255]
                     const float* __restrict__ lin_b,  // [1]
                     float* __restrict__ out)          // [B, 1, D] -> b*D + d
{
    __shared__ __align__(16) float sW[256];  // c[v]; c[0]=0
    __shared__ float sA[S][D];               // [s][d] = 0.5*k*w
    __shared__ float sC[S][D];               // [s][d] = -0.5*k*q

    const int tid = threadIdx.x;   // 128 threads
#pragma unroll
    for (int i = tid; i < 256; i += 128) {
        sW[i] = (i == 0) ? 0.0f : lin_w[i - 1];
        const int dd = i >> 3, ss = i & 7;   // i = d*8 + s matches flat [D,S]
        const float kh = 0.5f * k[i];
        sA[ss][dd] = kh * w[i];
        sC[ss][dd] = -kh * q[i];
    }
    __syncthreads();

    const int d = tid & 31;                  // lane = d
    const int warp = tid >> 5;               // 4 warps/block
    const int b0 = (blockIdx.x * 4 + warp) * T;

    // x rows b0..b0+1 (uniform across warp -> broadcast LDG.128)
    const float4* xp = reinterpret_cast<const float4*>(x + b0 * S);
    float xs[T][8];
#pragma unroll
    for (int r = 0; r < T; ++r) {
        const float4 a = xp[2 * r], bb = xp[2 * r + 1];
        xs[r][0] = a.x;  xs[r][1] = a.y;  xs[r][2] = a.z;  xs[r][3] = a.w;
        xs[r][4] = bb.x; xs[r][5] = bb.y; xs[r][6] = bb.z; xs[r][7] = bb.w;
    }

    // P[r][s] = sigmoid(k*(w*x-q))
    float P[T][8];
#pragma unroll
    for (int s = 0; s < 8; ++s) {
        const float A = sA[s][d];
        const float C = sC[s][d];
#pragma unroll
        for (int r = 0; r < T; ++r)
            P[r][s] = fast_sigmoid_prehalved(fmaf(A, xs[r][s], C));
    }

    // Inner Horner over lo = v&15 (bit0<->p7, bit1<->p6, bit2<->p5, bit3<->p4):
    //   inner[hi] = 15 FMA using c[hi*16 .. hi*16+15].
    // Outer Horner over hi (bit0<->p3, bit1<->p2, bit2<->p1, bit3<->p0),
    // with the first outer level (u[t] = inner[2t] + p3*inner[2t+1]) folded
    // into the hi-loop so only u[0..7] stays live per row.
    float u[T][8];
    float innerOdd[T];   // holds inner[2t] while computing inner[2t+1]
    const float4* W4 = reinterpret_cast<const float4*>(sW);
#pragma unroll
    for (int hi = 0; hi < 16; ++hi) {
        const float4 w0 = W4[hi * 4 + 0];
        const float4 w1 = W4[hi * 4 + 1];
        const float4 w2 = W4[hi * 4 + 2];
        const float4 w3 = W4[hi * 4 + 3];
#pragma unroll
        for (int r = 0; r < T; ++r) {
            const float p7 = P[r][7], p6 = P[r][6], p5 = P[r][5], p4 = P[r][4];
            // level A: split bit0 (p7)
            const float e0 = fmaf(p7, w0.y, w0.x);
            const float e1 = fmaf(p7, w0.w, w0.z);
            const float e2 = fmaf(p7, w1.y, w1.x);
            const float e3 = fmaf(p7, w1.w, w1.z);
            const float e4 = fmaf(p7, w2.y, w2.x);
            const float e5 = fmaf(p7, w2.w, w2.z);
            const float e6 = fmaf(p7, w3.y, w3.x);
            const float e7 = fmaf(p7, w3.w, w3.z);
            // level B: split bit1 (p6)
            const float f0 = fmaf(p6, e1, e0);
            const float f1 = fmaf(p6, e3, e2);
            const float f2 = fmaf(p6, e5, e4);
            const float f3 = fmaf(p6, e7, e6);
            // level C: split bit2 (p5)
            const float g0 = fmaf(p5, f1, f0);
            const float g1 = fmaf(p5, f3, f2);
            // level D: split bit3 (p4)
            const float inner = fmaf(p4, g1, g0);

            if ((hi & 1) == 0) {
                innerOdd[r] = inner;                       // stash inner[2t]
            } else {
                u[r][hi >> 1] = fmaf(P[r][3], inner, innerOdd[r]);
            }
        }
    }

    const float bias = lin_b[0];
#pragma unroll
    for (int r = 0; r < T; ++r) {
        const float p2 = P[r][2], p1 = P[r][1], p0 = P[r][0];
        const float v0 = fmaf(p2, u[r][1], u[r][0]);
        const float v1 = fmaf(p2, u[r][3], u[r][2]);
        const float v2 = fmaf(p2, u[r][5], u[r][4]);
        const float v3 = fmaf(p2, u[r][7], u[r][6]);
        const float w0 = fmaf(p1, v1, v0);
        const float w1 = fmaf(p1, v3, v2);
        const float res = fmaf(p0, w1, w0);
        out[(b0 + r) * D + d] = res + bias;
    }
}

extern "C" void kernel_launch(void* const* d_in, const int* in_sizes, int n_in,
                              void* d_out, int out_size) {
    const float* x     = (const float*)d_in[0];
    const float* k     = (const float*)d_in[1];
    const float* w     = (const float*)d_in[2];
    const float* q     = (const float*)d_in[3];
    // d_in[4] = mask (unused: fixed binary-expansion generation rule)
    const float* lin_w = (const float*)d_in[5];
    const float* lin_b = (const float*)d_in[6];
    float* out = (float*)d_out;

    // 128 threads = 4 warps; each warp: 2 batch rows -> 8 rows/block -> 1024 blocks
    dendrite_kernel<<<B / 8, 128>>>(x, k, w, q, lin_w, lin_b, out);
}